// round 1
// baseline (speedup 1.0000x reference)
#include <cuda_runtime.h>
#include <cuda_bf16.h>

#define N_NODES 50000
#define N_EDGES 1600000
#define BATCH 4
#define T_STEPS 50
#define DT 0.02f

// ---------------- static device scratch (no allocations allowed) ----------------
__device__ int    g_cnt[N_NODES];
__device__ int    g_row[N_NODES + 1];
__device__ int    g_cur[N_NODES];
__device__ int2   g_edges[N_EDGES];      // {src, weight-as-int-bits}, sorted by target
__device__ float  g_alpha[N_NODES];
__device__ float4 g_v[2][N_NODES];       // double-buffered state, node-major x 4 batches

// ---------------- preprocessing ----------------

__global__ void zero_cnt_kernel() {
    int n = blockIdx.x * blockDim.x + threadIdx.x;
    if (n < N_NODES) g_cnt[n] = 0;
}

__global__ void hist_kernel(const int* __restrict__ tgt) {
    int e = blockIdx.x * blockDim.x + threadIdx.x;
    if (e < N_EDGES) atomicAdd(&g_cnt[tgt[e]], 1);
}

// Single-CTA exclusive scan of g_cnt -> g_row (and g_cur copy). 1024 threads.
__global__ void scan_kernel() {
    __shared__ int wsum[32];
    __shared__ int carry_s;
    int tid = threadIdx.x, lane = tid & 31, wi = tid >> 5;
    if (tid == 0) carry_s = 0;
    __syncthreads();
    for (int base = 0; base < N_NODES; base += 1024) {
        int i = base + tid;
        int val = (i < N_NODES) ? g_cnt[i] : 0;
        int incl = val;
        #pragma unroll
        for (int d = 1; d < 32; d <<= 1) {
            int y = __shfl_up_sync(0xffffffffu, incl, d);
            if (lane >= d) incl += y;
        }
        if (lane == 31) wsum[wi] = incl;
        __syncthreads();
        if (wi == 0) {
            int s = wsum[lane];
            int inc2 = s;
            #pragma unroll
            for (int d = 1; d < 32; d <<= 1) {
                int y = __shfl_up_sync(0xffffffffu, inc2, d);
                if (lane >= d) inc2 += y;
            }
            wsum[lane] = inc2 - s;   // exclusive warp offsets
        }
        __syncthreads();
        int excl = carry_s + wsum[wi] + (incl - val);
        if (i < N_NODES) { g_row[i] = excl; g_cur[i] = excl; }
        int my_incl = excl + val;
        __syncthreads();
        if (tid == 1023) carry_s = my_incl;
        __syncthreads();
    }
    if (threadIdx.x == 0) g_row[N_NODES] = carry_s;   // == N_EDGES
}

__global__ void build_kernel(const int* __restrict__ src, const int* __restrict__ tgt,
                             const float* __restrict__ sign, const float* __restrict__ syn_cnt,
                             const float* __restrict__ syn_str) {
    int e = blockIdx.x * blockDim.x + threadIdx.x;
    if (e < N_EDGES) {
        float w = sign[e] * fmaxf(syn_cnt[e], 0.f) * fmaxf(syn_str[e], 0.f);
        int p = atomicAdd(&g_cur[tgt[e]], 1);
        g_edges[p] = make_int2(src[e], __float_as_int(w));
    }
}

__global__ void init_kernel(const float* __restrict__ bias, const float* __restrict__ tc) {
    int n = blockIdx.x * blockDim.x + threadIdx.x;
    if (n < N_NODES) {
        float tau = fmaxf(tc[n], DT);
        g_alpha[n] = DT / tau;
        float b = bias[n];
        g_v[0][n] = make_float4(b, b, b, b);
    }
}

// ---------------- fused per-step kernel ----------------
// CTA = 256 threads = 8 warps = 8 consecutive target nodes.
// Warp w accumulates the synaptic input for node (blockIdx.x*8 + w) over all 4 batches,
// then threads 0..31 do the Euler update + output write with coalesced access.
__global__ void __launch_bounds__(256) step_kernel(const float* __restrict__ x,
                                                   const float* __restrict__ bias,
                                                   float* __restrict__ out,
                                                   int t, int parity) {
    const int node0 = blockIdx.x * 8;
    const int w = threadIdx.x >> 5;
    const int lane = threadIdx.x & 31;
    const int n = node0 + w;

    const float4* __restrict__ vin = g_v[parity];
    float4* __restrict__ vout = g_v[parity ^ 1];

    int beg = g_row[n];
    int end = g_row[n + 1];

    float4 acc = make_float4(0.f, 0.f, 0.f, 0.f);
    for (int e = beg + lane; e < end; e += 32) {
        int2 ed = __ldg(&g_edges[e]);
        float wgt = __int_as_float(ed.y);
        float4 vs = __ldg(&vin[ed.x]);
        acc.x += wgt * fmaxf(vs.x, 0.f);
        acc.y += wgt * fmaxf(vs.y, 0.f);
        acc.z += wgt * fmaxf(vs.z, 0.f);
        acc.w += wgt * fmaxf(vs.w, 0.f);
    }
    #pragma unroll
    for (int d = 16; d; d >>= 1) {
        acc.x += __shfl_xor_sync(0xffffffffu, acc.x, d);
        acc.y += __shfl_xor_sync(0xffffffffu, acc.y, d);
        acc.z += __shfl_xor_sync(0xffffffffu, acc.z, d);
        acc.w += __shfl_xor_sync(0xffffffffu, acc.w, d);
    }

    __shared__ float sh[32];     // [node_in_block][batch] flattened
    if (lane == 0) {
        sh[w * 4 + 0] = acc.x;
        sh[w * 4 + 1] = acc.y;
        sh[w * 4 + 2] = acc.z;
        sh[w * 4 + 3] = acc.w;
    }
    __syncthreads();

    if (threadIdx.x < 32) {
        int b = threadIdx.x & 3;
        int j = threadIdx.x >> 2;
        int nn = node0 + j;
        const float* vinf = (const float*)vin;
        float vold = vinf[node0 * 4 + threadIdx.x];     // coalesced 128B
        float s    = sh[threadIdx.x];
        float a    = g_alpha[nn];
        float bi   = bias[nn];
        int   xi   = (b * T_STEPS + t) * N_NODES + nn;
        float xv   = x[xi];
        float vnew = vold + a * (-vold + bi + s + xv);
        ((float*)vout)[node0 * 4 + threadIdx.x] = vnew;  // coalesced 128B
        out[xi] = fmaxf(vnew, 0.f);                      // 4 x 32B sectors
    }
}

// ---------------- launch ----------------
extern "C" void kernel_launch(void* const* d_in, const int* in_sizes, int n_in,
                              void* d_out, int out_size) {
    const float* x            = (const float*)d_in[0];   // [B, T, N]
    const float* bias         = (const float*)d_in[1];   // [N]
    const float* time_const   = (const float*)d_in[2];   // [N]
    const float* sign         = (const float*)d_in[3];   // [E]
    const float* syn_count    = (const float*)d_in[4];   // [E]
    const float* syn_strength = (const float*)d_in[5];   // [E]
    const int*   src_idx      = (const int*)d_in[6];     // [E]
    const int*   tgt_idx      = (const int*)d_in[7];     // [E]
    float* out = (float*)d_out;                          // [B, T, N]

    const int TB = 256;
    zero_cnt_kernel<<<(N_NODES + TB - 1) / TB, TB>>>();
    hist_kernel<<<(N_EDGES + TB - 1) / TB, TB>>>(tgt_idx);
    scan_kernel<<<1, 1024>>>();
    build_kernel<<<(N_EDGES + TB - 1) / TB, TB>>>(src_idx, tgt_idx, sign, syn_count, syn_strength);
    init_kernel<<<(N_NODES + TB - 1) / TB, TB>>>(bias, time_const);

    for (int t = 0; t < T_STEPS; t++) {
        step_kernel<<<N_NODES / 8, 256>>>(x, bias, out, t, t & 1);
    }
}

// round 4
// speedup vs baseline: 1.2913x; 1.2913x over previous
#include <cuda_runtime.h>
#include <cuda_bf16.h>

#define N_NODES 50000
#define N_EDGES 1600000
#define BATCH 4
#define T_STEPS 50
#define DT 0.02f

// ---------------- static device scratch (no allocations allowed) ----------------
__device__ __align__(16) int   g_cnt[N_NODES];
__device__ int            g_row[N_NODES + 1];
__device__ int            g_cur[N_NODES];
__device__ unsigned short g_src16[N_EDGES];   // src node (fits: 50000 < 65536)
__device__ float          g_wgt[N_EDGES];     // edge weight, target-sorted
__device__ float2         g_ab[N_NODES];      // {alpha, alpha*bias}
__device__ float4         g_v[2][N_NODES];    // double-buffered state, node-major x 4 batches

// ---------------- preprocessing ----------------

__global__ void zero_cnt_kernel() {
    int n = blockIdx.x * blockDim.x + threadIdx.x;
    if (n < N_NODES) g_cnt[n] = 0;
}

__global__ void hist_kernel(const int* __restrict__ tgt) {
    int e = blockIdx.x * blockDim.x + threadIdx.x;
    if (e < N_EDGES) atomicAdd(&g_cnt[tgt[e]], 1);
}

// Single-CTA exclusive scan of g_cnt -> g_row/g_cur. 1024 threads, 4 elems/thread.
__global__ void scan_kernel() {
    __shared__ int wsum[32];
    __shared__ int carry_s;
    int tid = threadIdx.x, lane = tid & 31, wi = tid >> 5;
    if (tid == 0) carry_s = 0;
    __syncthreads();
    for (int base = 0; base < N_NODES; base += 4096) {
        int i0 = base + tid * 4;
        int4 c = make_int4(0, 0, 0, 0);
        if (i0 + 3 < N_NODES) {
            c = *(const int4*)&g_cnt[i0];
        } else {
            if (i0 + 0 < N_NODES) c.x = g_cnt[i0 + 0];
            if (i0 + 1 < N_NODES) c.y = g_cnt[i0 + 1];
            if (i0 + 2 < N_NODES) c.z = g_cnt[i0 + 2];
            if (i0 + 3 < N_NODES) c.w = g_cnt[i0 + 3];
        }
        int tot = c.x + c.y + c.z + c.w;
        int incl = tot;
        #pragma unroll
        for (int d = 1; d < 32; d <<= 1) {
            int y = __shfl_up_sync(0xffffffffu, incl, d);
            if (lane >= d) incl += y;
        }
        if (lane == 31) wsum[wi] = incl;
        __syncthreads();
        if (wi == 0) {
            int s = wsum[lane];
            int inc2 = s;
            #pragma unroll
            for (int d = 1; d < 32; d <<= 1) {
                int y = __shfl_up_sync(0xffffffffu, inc2, d);
                if (lane >= d) inc2 += y;
            }
            wsum[lane] = inc2 - s;   // exclusive warp offsets
        }
        __syncthreads();
        int excl = carry_s + wsum[wi] + (incl - tot);
        int e0 = excl;
        int e1 = e0 + c.x;
        int e2 = e1 + c.y;
        int e3 = e2 + c.z;
        if (i0 + 0 < N_NODES) { g_row[i0 + 0] = e0; g_cur[i0 + 0] = e0; }
        if (i0 + 1 < N_NODES) { g_row[i0 + 1] = e1; g_cur[i0 + 1] = e1; }
        if (i0 + 2 < N_NODES) { g_row[i0 + 2] = e2; g_cur[i0 + 2] = e2; }
        if (i0 + 3 < N_NODES) { g_row[i0 + 3] = e3; g_cur[i0 + 3] = e3; }
        __syncthreads();
        if (tid == 1023) carry_s = excl + tot;
        __syncthreads();
    }
    if (threadIdx.x == 0) g_row[N_NODES] = carry_s;   // == N_EDGES
}

__global__ void build_kernel(const int* __restrict__ src, const int* __restrict__ tgt,
                             const float* __restrict__ sign, const float* __restrict__ syn_cnt,
                             const float* __restrict__ syn_str) {
    int e = blockIdx.x * blockDim.x + threadIdx.x;
    if (e < N_EDGES) {
        float w = sign[e] * fmaxf(syn_cnt[e], 0.f) * fmaxf(syn_str[e], 0.f);
        int p = atomicAdd(&g_cur[tgt[e]], 1);
        g_src16[p] = (unsigned short)src[e];
        g_wgt[p] = w;
    }
}

__global__ void init_kernel(const float* __restrict__ bias, const float* __restrict__ tc) {
    int n = blockIdx.x * blockDim.x + threadIdx.x;
    if (n < N_NODES) {
        float tau = fmaxf(tc[n], DT);
        float a = DT / tau;
        float b = bias[n];
        g_ab[n] = make_float2(a, a * b);
        g_v[0][n] = make_float4(b, b, b, b);
    }
}

// ---------------- fused per-step kernel ----------------
// CTA = 256 threads = 32 nodes (8 lanes per node). 4x-unrolled gather loop for MLP.
__global__ void __launch_bounds__(256) step_kernel(const float* __restrict__ x,
                                                   float* __restrict__ out,
                                                   int t, int parity) {
    const int node0 = blockIdx.x * 32;
    const int tid = threadIdx.x;
    const int sub = tid & 7;
    const int oct = tid >> 3;    // node within CTA, 0..31
    const int n = node0 + oct;

    const float4* __restrict__ vin = g_v[parity];
    float4* __restrict__ vout = g_v[parity ^ 1];

    int beg = 0, end = 0;
    if (n < N_NODES) { beg = g_row[n]; end = g_row[n + 1]; }

    float4 acc = make_float4(0.f, 0.f, 0.f, 0.f);
    int e = beg + sub;

    // main loop: 4 edges per lane per iteration, 8 independent loads in flight
    while (e + 24 < end) {
        int s0 = __ldg(&g_src16[e]);
        int s1 = __ldg(&g_src16[e + 8]);
        int s2 = __ldg(&g_src16[e + 16]);
        int s3 = __ldg(&g_src16[e + 24]);
        float w0 = __ldg(&g_wgt[e]);
        float w1 = __ldg(&g_wgt[e + 8]);
        float w2 = __ldg(&g_wgt[e + 16]);
        float w3 = __ldg(&g_wgt[e + 24]);
        float4 a0 = __ldg(&vin[s0]);
        float4 a1 = __ldg(&vin[s1]);
        float4 a2 = __ldg(&vin[s2]);
        float4 a3 = __ldg(&vin[s3]);
        acc.x += w0 * fmaxf(a0.x, 0.f) + w1 * fmaxf(a1.x, 0.f)
               + w2 * fmaxf(a2.x, 0.f) + w3 * fmaxf(a3.x, 0.f);
        acc.y += w0 * fmaxf(a0.y, 0.f) + w1 * fmaxf(a1.y, 0.f)
               + w2 * fmaxf(a2.y, 0.f) + w3 * fmaxf(a3.y, 0.f);
        acc.z += w0 * fmaxf(a0.z, 0.f) + w1 * fmaxf(a1.z, 0.f)
               + w2 * fmaxf(a2.z, 0.f) + w3 * fmaxf(a3.z, 0.f);
        acc.w += w0 * fmaxf(a0.w, 0.f) + w1 * fmaxf(a1.w, 0.f)
               + w2 * fmaxf(a2.w, 0.f) + w3 * fmaxf(a3.w, 0.f);
        e += 32;
    }
    // remainder: up to 3 edges per lane
    while (e < end) {
        int s = __ldg(&g_src16[e]);
        float w = __ldg(&g_wgt[e]);
        float4 a = __ldg(&vin[s]);
        acc.x += w * fmaxf(a.x, 0.f);
        acc.y += w * fmaxf(a.y, 0.f);
        acc.z += w * fmaxf(a.z, 0.f);
        acc.w += w * fmaxf(a.w, 0.f);
        e += 8;
    }

    // octet reduction (3 rounds, stays inside each 8-lane group)
    #pragma unroll
    for (int d = 4; d; d >>= 1) {
        acc.x += __shfl_xor_sync(0xffffffffu, acc.x, d);
        acc.y += __shfl_xor_sync(0xffffffffu, acc.y, d);
        acc.z += __shfl_xor_sync(0xffffffffu, acc.z, d);
        acc.w += __shfl_xor_sync(0xffffffffu, acc.w, d);
    }

    __shared__ float sh[128];   // [node_in_cta][batch]
    if (sub == 0) {
        sh[oct * 4 + 0] = acc.x;
        sh[oct * 4 + 1] = acc.y;
        sh[oct * 4 + 2] = acc.z;
        sh[oct * 4 + 3] = acc.w;
    }
    __syncthreads();

    // epilogue: 128 threads = 32 nodes x 4 batches, fully coalesced v access
    if (tid < 128) {
        int j = tid >> 2;
        int b = tid & 3;
        int nn = node0 + j;
        if (nn < N_NODES) {
            float vold = ((const float*)vin)[node0 * 4 + tid];
            float s    = sh[tid];
            float2 ab  = g_ab[nn];
            int   xi   = (b * T_STEPS + t) * N_NODES + nn;
            float xv   = __ldg(&x[xi]);
            float vnew = vold + ab.x * (s + xv - vold) + ab.y;
            ((float*)vout)[node0 * 4 + tid] = vnew;
            out[xi] = fmaxf(vnew, 0.f);
        }
    }
}

// ---------------- launch ----------------
extern "C" void kernel_launch(void* const* d_in, const int* in_sizes, int n_in,
                              void* d_out, int out_size) {
    const float* x            = (const float*)d_in[0];   // [B, T, N]
    const float* bias         = (const float*)d_in[1];   // [N]
    const float* time_const   = (const float*)d_in[2];   // [N]
    const float* sign         = (const float*)d_in[3];   // [E]
    const float* syn_count    = (const float*)d_in[4];   // [E]
    const float* syn_strength = (const float*)d_in[5];   // [E]
    const int*   src_idx      = (const int*)d_in[6];     // [E]
    const int*   tgt_idx      = (const int*)d_in[7];     // [E]
    float* out = (float*)d_out;                          // [B, T, N]

    const int TB = 256;
    zero_cnt_kernel<<<(N_NODES + TB - 1) / TB, TB>>>();
    hist_kernel<<<(N_EDGES + TB - 1) / TB, TB>>>(tgt_idx);
    scan_kernel<<<1, 1024>>>();
    build_kernel<<<(N_EDGES + TB - 1) / TB, TB>>>(src_idx, tgt_idx, sign, syn_count, syn_strength);
    init_kernel<<<(N_NODES + TB - 1) / TB, TB>>>(bias, time_const);

    const int STEP_GRID = (N_NODES + 31) / 32;   // 1563
    for (int t = 0; t < T_STEPS; t++) {
        step_kernel<<<STEP_GRID, 256>>>(x, out, t, t & 1);
    }
}